// round 13
// baseline (speedup 1.0000x reference)
#include <cuda_runtime.h>
#include <math.h>

#define NB   4
#define NS   4224
#define ND   1024
#define NDM  64
#define NDK  128
#define NL   528
#define NSEG 8
#define NM   16
#define EPSV 1e-5f
#define GRID 128

typedef unsigned long long u64;

__device__ __forceinline__ u64 pk2(float lo, float hi) {
    u64 r; asm("mov.b64 %0,{%1,%2};" : "=l"(r) : "f"(lo), "f"(hi)); return r;
}
__device__ __forceinline__ void fma2(u64 &d, u64 a, u64 b) {
    asm("fma.rn.f32x2 %0,%1,%2,%0;" : "+l"(d) : "l"(a), "l"(b));
}
__device__ __forceinline__ float2 up2(u64 v) {
    float2 f; asm("mov.b64 {%0,%1},%2;" : "=f"(f.x), "=f"(f.y) : "l"(v)); return f;
}
__device__ __forceinline__ float tanh_hw(float x) {
    float r; asm("tanh.approx.f32 %0,%1;" : "=f"(r) : "f"(x)); return r;
}

// ---------------- device scratch ----------------
__device__ __align__(16) float g_Q [NB*NS*NDK];
__device__ __align__(16) float g_T [NB*NS*NDK];
__device__ __align__(16) float g_Kt[NB*NDK*NDK];     // [b][feat i][rank]
__device__ __align__(16) float g_NI[NB*NDK*ND];      // [b][rank][d]
__device__ __align__(16) float g_mem[NB*ND*NM];      // [b][d][m] col-major
__device__ __align__(16) float g_xp [NB*32*NM*NDM];  // x partials per 32-col slab
__device__ __align__(16) float g_tt [NB*NM*NDK];     // masked tt for next segment
__device__ unsigned g_bar = 0u;

// ---------------- grid barrier: scoped release/acquire, NO L1-flushing fence ----
// All cross-block mutable traffic in kLoop uses .cg (L2) loads/stores, so the
// gpu-scope release-arrive + acquire-poll suffices; no CCTL.IVALL is emitted.
__device__ __forceinline__ void gsync(unsigned tgt)
{
    __syncthreads();
    if (threadIdx.x == 0) {
        asm volatile("red.release.gpu.global.add.u32 [%0], 1;"
                     :: "l"(&g_bar) : "memory");
        unsigned v;
        int sp = 0;
        for (;;) {
            asm volatile("ld.acquire.gpu.global.u32 %0,[%1];"
                         : "=r"(v) : "l"(&g_bar) : "memory");
            if (v >= tgt) break;
            if (++sp > 512) __nanosleep(64);
        }
    }
    __syncthreads();
}

// ---------------- K0: Q = dpfp(hs @ W_mq); resets g_bar ----------------
__global__ void k0_projq(const float* __restrict__ hs, const float* __restrict__ Wmq)
{
    if (blockIdx.x == 0 && threadIdx.x == 0) g_bar = 0u;
    __shared__ float As[16*128];
    __shared__ float Bs[16*64];
    __shared__ float Xs[128*65];
    int tid = threadIdx.x;
    int rowBase = blockIdx.x * 128;
    int tx = tid & 15, ty = tid >> 4;
    u64 acc[4][4];
    #pragma unroll
    for (int p = 0; p < 4; p++)
        #pragma unroll
        for (int j = 0; j < 4; j++) acc[p][j] = 0ull;

    for (int k0 = 0; k0 < ND; k0 += 16) {
        #pragma unroll
        for (int it = 0; it < 2; it++) {
            int f = it*256 + tid;
            int row = f >> 2; int q = (f & 3) * 4;
            float4 v4 = *reinterpret_cast<const float4*>(
                &hs[(size_t)(rowBase + row)*ND + k0 + q]);
            As[(q+0)*128+row] = v4.x; As[(q+1)*128+row] = v4.y;
            As[(q+2)*128+row] = v4.z; As[(q+3)*128+row] = v4.w;
        }
        {
            int kr = tid >> 4; int c = (tid & 15) * 4;
            *reinterpret_cast<float4*>(&Bs[kr*64 + c]) =
                *reinterpret_cast<const float4*>(&Wmq[(size_t)(k0+kr)*NDM + c]);
        }
        __syncthreads();
        #pragma unroll
        for (int k = 0; k < 16; k++) {
            u64 a2[4];
            #pragma unroll
            for (int p = 0; p < 4; p++)
                a2[p] = *reinterpret_cast<const u64*>(&As[k*128 + ty*8 + 2*p]);
            #pragma unroll
            for (int j = 0; j < 4; j++) {
                float bv = Bs[k*64 + tx*4 + j];
                u64 b2 = pk2(bv, bv);
                #pragma unroll
                for (int p = 0; p < 4; p++) fma2(acc[p][j], a2[p], b2);
            }
        }
        __syncthreads();
    }
    #pragma unroll
    for (int p = 0; p < 4; p++)
        #pragma unroll
        for (int j = 0; j < 4; j++) {
            float2 f = up2(acc[p][j]);
            Xs[(ty*8+2*p  )*65 + tx*4 + j] = f.x;
            Xs[(ty*8+2*p+1)*65 + tx*4 + j] = f.y;
        }
    __syncthreads();
    #pragma unroll
    for (int t = 0; t < 64; t++) {
        int idx = t*256 + tid;
        int row = idx >> 7, i = idx & 127;
        int im1 = (i + 127) & 127;
        float a = (i  < 64) ? fmaxf( Xs[row*65 + i     ], 0.f)
                            : fmaxf(-Xs[row*65 + i - 64], 0.f);
        float b = (im1 < 64) ? fmaxf( Xs[row*65 + im1     ], 0.f)
                             : fmaxf(-Xs[row*65 + im1 - 64], 0.f);
        g_Q[(size_t)(rowBase + row)*NDK + i] = a*b;
    }
}

// ---------------- kLoop: fused recurrence, 128 persistent blocks ----------
// block = (b = blk>>5, ct = blk&31) owns cols [ct*32, ct*32+32)
__global__ void __launch_bounds__(256)
kLoop(const float* __restrict__ mo,  const float* __restrict__ Wmk,
      const float* __restrict__ Wmv, const float* __restrict__ Wmb,
      const float* __restrict__ bmb)
{
    __shared__ __align__(16) float S[10256];   // 41 KB
    int tid = threadIdx.x;
    int blk = blockIdx.x;
    int b  = blk >> 5;
    int ct = blk & 31;
    int cb = ct * 32;
    const float* NIb = &g_NI[(size_t)b*NDK*ND];
    const float* Ktb = &g_Kt[(size_t)b*NDK*NDK];
    unsigned tgt = GRID;

    for (int seg = 0; seg < NSEG; seg++) {
        int R = seg * NM;
        size_t rbase = (size_t)b*NS + seg*NL + (NL - NM);

        // ===== Phase A: den + assoc -> mem (col-major); x partials =====
        {
            float* ttm = S;          // [0,2048)
            float* dn  = S + 2048;   // 16
            float* Ms  = S + 2064;   // 512
            float* NIa = S + 2576;   // up to 3584 (bulk NI; also den scratch)
            if (seg > 0) {
                for (int f = tid; f < 512; f += 256)
                    *reinterpret_cast<float4*>(&ttm[f*4]) =
                        __ldcg(reinterpret_cast<const float4*>(&g_tt[b*2048 + f*4]));
            } else {
                for (int f = tid; f < 512; f += 256)
                    *reinterpret_cast<float4*>(&ttm[f*4]) = make_float4(0.f,0.f,0.f,0.f);
            }
            __syncthreads();
            if (tid < 128) {         // den = rowsum(ttm)
                int m = tid >> 3, p = tid & 7;
                float s = 0.f;
                #pragma unroll
                for (int r = p*16; r < p*16 + 16; r++) s += ttm[m*128 + r];
                NIa[tid] = s;
            }
            __syncthreads();
            if (tid < NM) {
                float s = 0.f;
                #pragma unroll
                for (int j2 = 0; j2 < 8; j2++) s += NIa[tid*8 + j2];
                dn[tid] = s + EPSV;
            }
            __syncthreads();
            // bulk NI load (L2-coherent: written by other blocks via __stcg)
            for (int f = tid; f < R*8; f += 256) {
                int r = f >> 3, q = (f & 7)*4;
                *reinterpret_cast<float4*>(&NIa[f*4]) =
                    __ldcg(reinterpret_cast<const float4*>(
                        &NIb[(size_t)r*ND + cb + q]));
            }
            __syncthreads();
            int m = tid >> 4, cp = tid & 15, c2 = cp*2;
            u64 acc = 0ull;
            const u64* NIu = reinterpret_cast<const u64*>(NIa);
            #pragma unroll 8
            for (int r = 0; r < R; r++) {
                float t = ttm[m*128 + r];
                fma2(acc, pk2(t, t), NIu[r*16 + cp]);
            }
            float2 av = up2(acc);
            float inv = 1.f/dn[m];
            float2 mv2 = *reinterpret_cast<const float2*>(&mo[(rbase+m)*ND + cb + c2]);
            float mv0 = av.x*inv + mv2.x;
            float mv1 = av.y*inv + mv2.y;
            Ms[m*32 + c2    ] = mv0;
            Ms[m*32 + c2 + 1] = mv1;
            __stcg(&g_mem[((size_t)b*ND + cb + c2    )*NM + m], mv0);
            __stcg(&g_mem[((size_t)b*ND + cb + c2 + 1)*NM + m], mv1);
            __syncthreads();
            int j = tid & 63, mg = tid >> 6;
            float a4[4] = {0.f, 0.f, 0.f, 0.f};
            #pragma unroll
            for (int cc = 0; cc < 32; cc++) {
                float w = Wmk[(size_t)(cb + cc)*NDM + j];
                #pragma unroll
                for (int i = 0; i < 4; i++) a4[i] += Ms[(mg*4+i)*32 + cc]*w;
            }
            #pragma unroll
            for (int i = 0; i < 4; i++)
                __stcg(&g_xp[((size_t)(b*32 + ct)*NM + mg*4 + i)*NDM + j], a4[i]);
        }
        gsync(tgt); tgt += GRID;

        // ===== Phase C: local B + prev + GEMM + NI + distributed tail =====
        {
            float* kvs = S;          // [0,2048) live through tail
            float* xsm = S + 2048;   // 1024 (then t2s)
            float* t2s = S + 2048;   // 2048
            float* kzf = S + 4096;   // 16
            float* NIa = S + 4112;   // 3584 (bulk NI; then Ach 4096)
            float* Ach = S + 4112;   // 4096
            float* red = S + 8208;   // 128 (then pp 2048)
            float* pp  = S + 8208;   // 2048

            // --- x reduce (float4, 32 loads) ---
            {
                float4 s4 = make_float4(0.f, 0.f, 0.f, 0.f);
                #pragma unroll 4
                for (int p = 0; p < 32; p++) {
                    float4 v = __ldcg(reinterpret_cast<const float4*>(
                        &g_xp[((size_t)(b*32 + p))*1024 + tid*4]));
                    s4.x += v.x; s4.y += v.y; s4.z += v.z; s4.w += v.w;
                }
                *reinterpret_cast<float4*>(&xsm[tid*4]) = s4;
            }
            __syncthreads();
            // --- dpfp -> kvs; ct==0 writes Kt column ---
            #pragma unroll
            for (int it = 0; it < 8; it++) {
                int f = it*256 + tid;
                int m = f >> 7, i = f & 127;
                int im1 = (i + 127) & 127;
                float a  = (i  < 64) ? fmaxf( xsm[m*64 + i     ], 0.f)
                                     : fmaxf(-xsm[m*64 + i - 64], 0.f);
                float b2 = (im1< 64) ? fmaxf( xsm[m*64 + im1     ], 0.f)
                                     : fmaxf(-xsm[m*64 + im1 - 64], 0.f);
                float kk = a*b2;
                kvs[m*128 + i] = kk;
                if (ct == 0)
                    __stcg(&g_Kt[(size_t)b*NDK*NDK + (size_t)i*NDK + (R + m)], kk);
            }
            __syncthreads();
            // --- t2 = k @ Kt_old (masked) ---
            {
                int r = tid & 127, h = tid >> 7;
                float a[16];
                #pragma unroll
                for (int m = 0; m < 16; m++) a[m] = 0.f;
                if (r < R) {
                    #pragma unroll 8
                    for (int i = h*64; i < h*64 + 64; i++) {
                        float kt = __ldcg(&Ktb[i*128 + r]);
                        #pragma unroll
                        for (int m = 0; m < 16; m++) a[m] += kvs[m*128 + i]*kt;
                    }
                }
                #pragma unroll
                for (int m = 0; m < 16; m++) Ach[(h*16 + m)*128 + r] = a[m];
            }
            __syncthreads();
            if (tid < 128) {
                int r = tid;
                #pragma unroll
                for (int m = 0; m < 16; m++)
                    t2s[m*128 + r] = Ach[m*128 + r] + Ach[(16 + m)*128 + r];
            }
            __syncthreads();
            if (tid < 128) {
                int m = tid >> 3, p = tid & 7;
                float s = 0.f;
                #pragma unroll
                for (int r = p*16; r < p*16 + 16; r++) s += t2s[m*128 + r];
                red[tid] = s;
            }
            __syncthreads();
            if (tid < NM) {
                float s = 0.f;
                #pragma unroll
                for (int j2 = 0; j2 < 8; j2++) s += red[tid*8 + j2];
                kzf[tid] = s + EPSV;
            }
            __syncthreads();

            // --- prev: bulk NI load (L2-coherent) then sync-free fma2 ---
            for (int f = tid; f < R*8; f += 256) {
                int r = f >> 3, q = (f & 7)*4;
                *reinterpret_cast<float4*>(&NIa[f*4]) =
                    __ldcg(reinterpret_cast<const float4*>(
                        &NIb[(size_t)r*ND + cb + q]));
            }
            __syncthreads();
            int m = tid >> 4, cp = tid & 15, c2 = cp*2;
            u64 accp = 0ull;
            {
                const u64* NIu = reinterpret_cast<const u64*>(NIa);
                #pragma unroll 8
                for (int r = 0; r < R; r++) {
                    float t = t2s[m*128 + r];
                    fma2(accp, pk2(t, t), NIu[r*16 + cp]);
                }
            }
            float2 pv = up2(accp);
            float invkz = 1.f/kzf[m];
            pv.x *= invkz; pv.y *= invkz;
            __syncthreads();

            // --- k-split v/gate GEMM ---
            int kq = tid >> 5, cl = tid & 31;
            u64 accv[8], accb[8];
            #pragma unroll
            for (int mp = 0; mp < 8; mp++) { accv[mp] = 0ull; accb[mp] = 0ull; }
            const float* gmB = &g_mem[(size_t)b*ND*NM];
            const float* WvB = &Wmv[cb + cl];
            const float* WbB = &Wmb[cb + cl];
            for (int ch = 0; ch < 4; ch++) {
                int k0g = ch*256;
                #pragma unroll
                for (int it = 0; it < 4; it++) {
                    int f = it*256 + tid;
                    *reinterpret_cast<float4*>(&Ach[f*4]) =
                        __ldcg(reinterpret_cast<const float4*>(
                            &gmB[(size_t)k0g*NM + f*4]));
                }
                __syncthreads();
                const u64* AchU = reinterpret_cast<const u64*>(Ach);
                #pragma unroll 8
                for (int kk = 0; kk < 32; kk++) {
                    int k = kq*32 + kk;
                    float wv = WvB[(size_t)(k0g + k)*ND];
                    float wb = WbB[(size_t)(k0g + k)*ND];
                    u64 wv2 = pk2(wv, wv), wb2 = pk2(wb, wb);
                    #pragma unroll
                    for (int mp = 0; mp < 8; mp++) {
                        u64 am = AchU[k*8 + mp];
                        fma2(accv[mp], am, wv2);
                        fma2(accb[mp], am, wb2);
                    }
                }
                __syncthreads();
            }
            // --- two-round kq reduction (V) ---
            u64* ppu = reinterpret_cast<u64*>(pp);
            if (kq >= 4) {
                #pragma unroll
                for (int mp = 0; mp < 8; mp++) ppu[((kq-4)*8 + mp)*32 + cl] = accv[mp];
            }
            __syncthreads();
            if (kq < 4) {
                #pragma unroll
                for (int mp = 0; mp < 8; mp++) {
                    float2 x = up2(accv[mp]), y = up2(ppu[(kq*8 + mp)*32 + cl]);
                    ppu[(kq*8 + mp)*32 + cl] = pk2(x.x + y.x, x.y + y.y);
                }
            }
            __syncthreads();
            float vV0 = 0.f, vV1 = 0.f;
            {
                int mh = m >> 1, hf = m & 1;
                #pragma unroll
                for (int q = 0; q < 4; q++) {
                    vV0 += pp[((q*8 + mh)*32 + c2    )*2 + hf];
                    vV1 += pp[((q*8 + mh)*32 + c2 + 1)*2 + hf];
                }
            }
            __syncthreads();
            // --- two-round kq reduction (B) ---
            if (kq >= 4) {
                #pragma unroll
                for (int mp = 0; mp < 8; mp++) ppu[((kq-4)*8 + mp)*32 + cl] = accb[mp];
            }
            __syncthreads();
            if (kq < 4) {
                #pragma unroll
                for (int mp = 0; mp < 8; mp++) {
                    float2 x = up2(accb[mp]), y = up2(ppu[(kq*8 + mp)*32 + cl]);
                    ppu[(kq*8 + mp)*32 + cl] = pk2(x.x + y.x, x.y + y.y);
                }
            }
            __syncthreads();
            float vB0 = 0.f, vB1 = 0.f;
            {
                int mh = m >> 1, hf = m & 1;
                #pragma unroll
                for (int q = 0; q < 4; q++) {
                    vB0 += pp[((q*8 + mh)*32 + c2    )*2 + hf];
                    vB1 += pp[((q*8 + mh)*32 + c2 + 1)*2 + hf];
                }
            }
            float2 bias = *reinterpret_cast<const float2*>(&bmb[cb + c2]);
            float g0 = 1.f/(1.f + expf(-(vB0 + bias.x)));
            float g1 = 1.f/(1.f + expf(-(vB1 + bias.y)));
            float2 o = make_float2(g0*(vV0 - pv.x), g1*(vV1 - pv.y));
            __stcg(reinterpret_cast<float2*>(
                &g_NI[((size_t)b*NDK + R + m)*ND + cb + c2]), o);
            __syncthreads();

            // --- distributed tail (ct<4): tt for next segment, 32 ranks each ---
            if (ct < 4 && seg < NSEG-1) {
                float* qs  = S + 2048;   // t2s dead
                float* ph2 = S + 4112;   // Ach dead
                int r0t = ct*32;
                size_t rb2 = (size_t)b*NS + (seg+1)*NL + (NL - NM);
                #pragma unroll
                for (int it = 0; it < 2; it++) {
                    int f = it*256 + tid;
                    int m2 = f >> 5; int qo = (f & 31) * 4;
                    *reinterpret_cast<float4*>(&qs[m2*128 + qo]) =
                        *reinterpret_cast<const float4*>(&g_Q[(rb2 + m2)*NDK + qo]);
                }
                __syncthreads();
                {
                    int rl = tid & 31, h = tid >> 5;
                    int r = r0t + rl;
                    float a[16];
                    #pragma unroll
                    for (int m2 = 0; m2 < 16; m2++) a[m2] = 0.f;
                    if (r < R) {
                        #pragma unroll 8
                        for (int i = h*16; i < h*16 + 16; i++) {
                            float kt = __ldcg(&Ktb[i*128 + r]);
                            #pragma unroll
                            for (int m2 = 0; m2 < 16; m2++) a[m2] += qs[m2*128 + i]*kt;
                        }
                    } else if (r < R + NM) {
                        const float* kcol = &kvs[(r - R)*128];
                        #pragma unroll 8
                        for (int i = h*16; i < h*16 + 16; i++) {
                            float kt = kcol[i];
                            #pragma unroll
                            for (int m2 = 0; m2 < 16; m2++) a[m2] += qs[m2*128 + i]*kt;
                        }
                    }
                    #pragma unroll
                    for (int m2 = 0; m2 < 16; m2++) ph2[(h*16 + m2)*32 + rl] = a[m2];
                }
                __syncthreads();
                #pragma unroll
                for (int pr = 0; pr < 2; pr++) {
                    int f = pr*256 + tid;          // f = m2*32 + rl
                    int m2 = f >> 5, rl = f & 31;
                    float s = 0.f;
                    #pragma unroll
                    for (int h = 0; h < 8; h++) s += ph2[(h*16 + m2)*32 + rl];
                    __stcg(&g_tt[(b*NM + m2)*NDK + r0t + rl], s);
                }
            }
        }
        if (seg < NSEG-1) { gsync(tgt); tgt += GRID; }
    }
}

// ---------------- kT: T = mask(Q @ K^T)/den (zero fast path) ----------------
__global__ void kT()
{
    __shared__ float As[32*64];
    __shared__ float Bs[32*128];
    int tid = threadIdx.x;
    int r0 = blockIdx.x * 64;
    int b  = blockIdx.y;
    int maskR_max = ((r0 + 63)/NL)*NM;
    if (maskR_max == 0) {
        #pragma unroll
        for (int it = 0; it < 8; it++) {
            int f = it*256 + tid;
            int row = f >> 5; int c = (f & 31)*4;
            *reinterpret_cast<float4*>(&g_T[((size_t)b*NS + r0 + row)*NDK + c]) =
                make_float4(0.f, 0.f, 0.f, 0.f);
        }
        return;
    }
    int tx = tid & 15, ty = tid >> 4;
    u64 acc[4][4];
    #pragma unroll
    for (int i = 0; i < 4; i++)
        #pragma unroll
        for (int j = 0; j < 4; j++) acc[i][j] = 0ull;

    for (int k0 = 0; k0 < NDK; k0 += 32) {
        #pragma unroll
        for (int it = 0; it < 2; it++) {
            int f = it*256 + tid;
            int r = f >> 3; int q = (f & 7) * 4;
            float4 v4 = *reinterpret_cast<const float4*>(
                &g_Q[((size_t)b*NS + r0 + r)*NDK + k0 + q]);
            As[(q+0)*64+r] = v4.x; As[(q+1)*64+r] = v4.y;
            As[(q+2)*64+r] = v4.z; As[(q+3)*64+r] = v4.w;
        }
        #pragma unroll
        for (int it = 0; it < 4; it++) {
            int f = it*256 + tid;
            int kr = f >> 5; int c = (f & 31) * 4;
            *reinterpret_cast<float4*>(&Bs[kr*128 + c]) =
                *reinterpret_cast<const float4*>(&g_Kt[(size_t)b*NDK*NDK + (size_t)(k0+kr)*NDK + c]);
        }
        __syncthreads();
        #pragma unroll
        for (int k = 0; k < 32; k++) {
            u64 a2[4], bv[4];
            #pragma unroll
            for (int i = 0; i < 4; i++) {
                float a = As[k*64 + ty*4 + i];
                a2[i] = pk2(a, a);
            }
            #pragma unroll
            for (int j = 0; j < 4; j++)
                bv[j] = *reinterpret_cast<const u64*>(&Bs[k*128 + tx*8 + 2*j]);
            #pragma unroll
            for (int i = 0; i < 4; i++)
                #pragma unroll
                for (int j = 0; j < 4; j++) fma2(acc[i][j], a2[i], bv[j]);
        }
        __syncthreads();
    }
    #pragma unroll
    for (int i = 0; i < 4; i++) {
        int row = r0 + ty*4 + i;
        int maskR = (row / NL) * NM;
        float2 tv[4];
        float rsum = 0.f;
        #pragma unroll
        for (int j = 0; j < 4; j++) {
            float2 f = up2(acc[i][j]);
            int c0 = tx*8 + 2*j;
            if (c0     >= maskR) f.x = 0.f;
            if (c0 + 1 >= maskR) f.y = 0.f;
            rsum += f.x + f.y;
            tv[j] = f;
        }
        #pragma unroll
        for (int off = 1; off < 16; off <<= 1)
            rsum += __shfl_xor_sync(0xffffffffu, rsum, off);
        float inv = 1.f/(rsum + EPSV);
        #pragma unroll
        for (int j = 0; j < 4; j++) {
            float2 o = make_float2(tv[j].x*inv, tv[j].y*inv);
            *reinterpret_cast<float2*>(&g_T[((size_t)b*NS + row)*NDK + tx*8 + 2*j]) = o;
        }
    }
}

// ---------------- k4: out = mo + tanh(T @ NI); rank-bounded K ----------------
__global__ void __launch_bounds__(256) k4_out(const float* __restrict__ mo,
                                              float* __restrict__ out)
{
    __shared__ float As[32*128];
    __shared__ float Bs[32*128];
    int tid = threadIdx.x;
    int c0 = blockIdx.x * 128;
    int r0 = blockIdx.y * 128;
    int b  = blockIdx.z;
    int kmax = ((r0 + 127)/NL)*NM;
    if (kmax == 0) {
        #pragma unroll
        for (int it = 0; it < 16; it++) {
            int f = it*256 + tid;
            int row = f >> 5; int c = (f & 31)*4;
            size_t ix = ((size_t)b*NS + r0 + row)*ND + c0 + c;
            *reinterpret_cast<float4*>(&out[ix]) =
                *reinterpret_cast<const float4*>(&mo[ix]);
        }
        return;
    }
    int kup = (kmax + 31) & ~31;
    int w = tid >> 5, lane = tid & 31;
    u64 acc[8][4];
    #pragma unroll
    for (int rp = 0; rp < 8; rp++)
        #pragma unroll
        for (int j = 0; j < 4; j++) acc[rp][j] = 0ull;

    for (int k0 = 0; k0 < kup; k0 += 32) {
        #pragma unroll
        for (int it = 0; it < 4; it++) {
            int f = it*256 + tid;
            int row = f >> 3; int q = (f & 7) * 4;
            float4 v4 = *reinterpret_cast<const float4*>(
                &g_T[((size_t)b*NS + r0 + row)*NDK + k0 + q]);
            As[(q+0)*128+row] = v4.x; As[(q+1)*128+row] = v4.y;
            As[(q+2)*128+row] = v4.z; As[(q+3)*128+row] = v4.w;
        }
        #pragma unroll
        for (int it = 0; it < 4; it++) {
            int f = it*256 + tid;
            int kr = f >> 5; int c = (f & 31) * 4;
            *reinterpret_cast<float4*>(&Bs[kr*128 + c]) =
                *reinterpret_cast<const float4*>(
                    &g_NI[(size_t)b*NDK*ND + (size_t)(k0+kr)*ND + c0 + c]);
        }
        __syncthreads();
        #pragma unroll
        for (int k = 0; k < 32; k++) {
            u64 a2[8];
            #pragma unroll
            for (int rp = 0; rp < 8; rp++)
                a2[rp] = *reinterpret_cast<const u64*>(&As[k*128 + w*16 + 2*rp]);
            #pragma unroll
            for (int j = 0; j < 4; j++) {
                float bv = Bs[k*128 + lane + 32*j];
                u64 b2 = pk2(bv, bv);
                #pragma unroll
                for (int rp = 0; rp < 8; rp++) fma2(acc[rp][j], a2[rp], b2);
            }
        }
        __syncthreads();
    }
    #pragma unroll
    for (int rp = 0; rp < 8; rp++) {
        int r = r0 + w*16 + 2*rp;
        #pragma unroll
        for (int j = 0; j < 4; j++) {
            int c = c0 + lane + 32*j;
            float2 f = up2(acc[rp][j]);
            size_t i0 = ((size_t)b*NS + r)*ND + c;
            size_t i1 = i0 + ND;
            out[i0] = mo[i0] + tanh_hw(f.x);
            out[i1] = mo[i1] + tanh_hw(f.y);
        }
    }
}

// ---------------- launch ----------------
extern "C" void kernel_launch(void* const* d_in, const int* in_sizes, int n_in,
                              void* d_out, int out_size)
{
    const float* hs  = (const float*)d_in[0];
    const float* mo  = (const float*)d_in[1];
    const float* Wmq = (const float*)d_in[2];
    const float* Wmk = (const float*)d_in[3];
    const float* Wmv = (const float*)d_in[4];
    const float* Wmb = (const float*)d_in[5];
    const float* bmb = (const float*)d_in[6];
    float* out = (float*)d_out;

    k0_projq<<<132, 256>>>(hs, Wmq);
    kLoop<<<GRID, 256>>>(mo, Wmk, Wmv, Wmb, bmb);
    kT<<<dim3(66, 4), 256>>>();
    k4_out<<<dim3(8, 33, 4), 256>>>(mo, out);
}

// round 15
// speedup vs baseline: 1.1181x; 1.1181x over previous
#include <cuda_runtime.h>
#include <math.h>

#define NB   4
#define NS   4224
#define ND   1024
#define NDM  64
#define NDK  128
#define NL   528
#define NSEG 8
#define NM   16
#define EPSV 1e-5f

typedef unsigned long long u64;

__device__ __forceinline__ u64 pk2(float lo, float hi) {
    u64 r; asm("mov.b64 %0,{%1,%2};" : "=l"(r) : "f"(lo), "f"(hi)); return r;
}
__device__ __forceinline__ void fma2(u64 &d, u64 a, u64 b) {
    asm("fma.rn.f32x2 %0,%1,%2,%0;" : "+l"(d) : "l"(a), "l"(b));
}
__device__ __forceinline__ float2 up2(u64 v) {
    float2 f; asm("mov.b64 {%0,%1},%2;" : "=f"(f.x), "=f"(f.y) : "l"(v)); return f;
}
__device__ __forceinline__ float tanh_hw(float x) {
    float r; asm("tanh.approx.f32 %0,%1;" : "=f"(r) : "f"(x)); return r;
}

// ---------------- device scratch ----------------
__device__ __align__(16) float g_Q [NB*NS*NDK];
__device__ __align__(16) float g_T [NB*NS*NDK];
__device__ __align__(16) float g_Kt[NB*NDK*NDK];     // [b][feat i][rank]
__device__ __align__(16) float g_NI[NB*NDK*ND];      // [b][rank][d]
__device__ __align__(16) float g_mem[NB*ND*NM];      // [b][d][m] col-major
__device__ __align__(16) float g_xp [NB*32*NM*NDM];  // x partials per 32-col slab
__device__ __align__(16) float g_tt [NB*NM*NDK];     // masked tt for next segment

// ---------------- K0: Q = dpfp(hs @ W_mq) ----------------
__global__ void k0_projq(const float* __restrict__ hs, const float* __restrict__ Wmq)
{
    __shared__ float As[16*128];
    __shared__ float Bs[16*64];
    __shared__ float Xs[128*65];
    int tid = threadIdx.x;
    int rowBase = blockIdx.x * 128;
    int tx = tid & 15, ty = tid >> 4;
    u64 acc[4][4];
    #pragma unroll
    for (int p = 0; p < 4; p++)
        #pragma unroll
        for (int j = 0; j < 4; j++) acc[p][j] = 0ull;

    for (int k0 = 0; k0 < ND; k0 += 16) {
        #pragma unroll
        for (int it = 0; it < 2; it++) {
            int f = it*256 + tid;
            int row = f >> 2; int q = (f & 3) * 4;
            float4 v4 = *reinterpret_cast<const float4*>(
                &hs[(size_t)(rowBase + row)*ND + k0 + q]);
            As[(q+0)*128+row] = v4.x; As[(q+1)*128+row] = v4.y;
            As[(q+2)*128+row] = v4.z; As[(q+3)*128+row] = v4.w;
        }
        {
            int kr = tid >> 4; int c = (tid & 15) * 4;
            *reinterpret_cast<float4*>(&Bs[kr*64 + c]) =
                *reinterpret_cast<const float4*>(&Wmq[(size_t)(k0+kr)*NDM + c]);
        }
        __syncthreads();
        #pragma unroll
        for (int k = 0; k < 16; k++) {
            u64 a2[4];
            #pragma unroll
            for (int p = 0; p < 4; p++)
                a2[p] = *reinterpret_cast<const u64*>(&As[k*128 + ty*8 + 2*p]);
            #pragma unroll
            for (int j = 0; j < 4; j++) {
                float bv = Bs[k*64 + tx*4 + j];
                u64 b2 = pk2(bv, bv);
                #pragma unroll
                for (int p = 0; p < 4; p++) fma2(acc[p][j], a2[p], b2);
            }
        }
        __syncthreads();
    }
    #pragma unroll
    for (int p = 0; p < 4; p++)
        #pragma unroll
        for (int j = 0; j < 4; j++) {
            float2 f = up2(acc[p][j]);
            Xs[(ty*8+2*p  )*65 + tx*4 + j] = f.x;
            Xs[(ty*8+2*p+1)*65 + tx*4 + j] = f.y;
        }
    __syncthreads();
    #pragma unroll
    for (int t = 0; t < 64; t++) {
        int idx = t*256 + tid;
        int row = idx >> 7, i = idx & 127;
        int im1 = (i + 127) & 127;
        float a = (i  < 64) ? fmaxf( Xs[row*65 + i     ], 0.f)
                            : fmaxf(-Xs[row*65 + i - 64], 0.f);
        float b = (im1 < 64) ? fmaxf( Xs[row*65 + im1     ], 0.f)
                             : fmaxf(-Xs[row*65 + im1 - 64], 0.f);
        g_Q[(size_t)(rowBase + row)*NDK + i] = a*b;
    }
}

// ---------------- kA: den + assoc -> mem (col-major); x partials ----------------
// grid 128: block = (b = blk>>5, ct = blk&31) owns cols [ct*32, ct*32+32)
__global__ void __launch_bounds__(256)
kA(const float* __restrict__ mo, const float* __restrict__ Wmk, int seg)
{
    __shared__ __align__(16) float S[6160];
    float* ttm = S;          // 2048
    float* dn  = S + 2048;   // 16
    float* Ms  = S + 2064;   // 512
    float* NIa = S + 2576;   // 3584
    int tid = threadIdx.x;
    int blk = blockIdx.x;
    int b  = blk >> 5;
    int ct = blk & 31;
    int cb = ct * 32;
    int R = seg * NM;
    size_t rbase = (size_t)b*NS + seg*NL + (NL - NM);
    const float* NIb = &g_NI[(size_t)b*NDK*ND];

    if (seg > 0) {
        for (int f = tid; f < 512; f += 256)
            *reinterpret_cast<float4*>(&ttm[f*4]) =
                __ldcg(reinterpret_cast<const float4*>(&g_tt[b*2048 + f*4]));
    } else {
        for (int f = tid; f < 512; f += 256)
            *reinterpret_cast<float4*>(&ttm[f*4]) = make_float4(0.f,0.f,0.f,0.f);
    }
    __syncthreads();
    if (tid < 128) {             // den = rowsum(ttm)
        int m = tid >> 3, p = tid & 7;
        float s = 0.f;
        #pragma unroll
        for (int r = p*16; r < p*16 + 16; r++) s += ttm[m*128 + r];
        NIa[tid] = s;
    }
    __syncthreads();
    if (tid < NM) {
        float s = 0.f;
        #pragma unroll
        for (int j2 = 0; j2 < 8; j2++) s += NIa[tid*8 + j2];
        dn[tid] = s + EPSV;
    }
    __syncthreads();
    for (int f = tid; f < R*8; f += 256) {     // bulk NI load
        int r = f >> 3, q = (f & 7)*4;
        *reinterpret_cast<float4*>(&NIa[f*4]) =
            __ldcg(reinterpret_cast<const float4*>(&NIb[(size_t)r*ND + cb + q]));
    }
    __syncthreads();
    int m = tid >> 4, cp = tid & 15, c2 = cp*2;
    u64 acc = 0ull;
    const u64* NIu = reinterpret_cast<const u64*>(NIa);
    #pragma unroll 8
    for (int r = 0; r < R; r++) {
        float t = ttm[m*128 + r];
        fma2(acc, pk2(t, t), NIu[r*16 + cp]);
    }
    float2 av = up2(acc);
    float inv = 1.f/dn[m];
    float2 mv2 = *reinterpret_cast<const float2*>(&mo[(rbase+m)*ND + cb + c2]);
    float mv0 = av.x*inv + mv2.x;
    float mv1 = av.y*inv + mv2.y;
    Ms[m*32 + c2    ] = mv0;
    Ms[m*32 + c2 + 1] = mv1;
    __stcg(&g_mem[((size_t)b*ND + cb + c2    )*NM + m], mv0);
    __stcg(&g_mem[((size_t)b*ND + cb + c2 + 1)*NM + m], mv1);
    __syncthreads();
    int j = tid & 63, mg = tid >> 6;
    float a4[4] = {0.f, 0.f, 0.f, 0.f};
    #pragma unroll
    for (int cc = 0; cc < 32; cc++) {
        float w = Wmk[(size_t)(cb + cc)*NDM + j];
        #pragma unroll
        for (int i = 0; i < 4; i++) a4[i] += Ms[(mg*4+i)*32 + cc]*w;
    }
    #pragma unroll
    for (int i = 0; i < 4; i++)
        __stcg(&g_xp[((size_t)(b*32 + ct)*NM + mg*4 + i)*NDM + j], a4[i]);
}

// ---------------- kC: local k + prev + v/gate GEMM + NI + distributed tail -----
// grid 128: block = (b, ct) as above; tail: each block owns 4 tt ranks.
__global__ void __launch_bounds__(256)
kC(const float* __restrict__ Wmv, const float* __restrict__ Wmb,
   const float* __restrict__ bmb, int seg)
{
    __shared__ __align__(16) float S[10256];
    float* kvs = S;          // 2048 (live through tail)
    float* xsm = S + 2048;   // 1024 (then t2s)
    float* t2s = S + 2048;   // 2048
    float* kzf = S + 4096;   // 16
    float* NIa = S + 4112;   // 3584 (then Ach 4096)
    float* Ach = S + 4112;   // 4096
    float* red = S + 8208;   // 128 (then pp 2048)
    float* pp  = S + 8208;   // 2048
    int tid = threadIdx.x;
    int blk = blockIdx.x;
    int b  = blk >> 5;
    int ct = blk & 31;
    int cb = ct * 32;
    int R = seg * NM;
    const float* NIb = &g_NI[(size_t)b*NDK*ND];
    const float* Ktb = &g_Kt[(size_t)b*NDK*NDK];

    // --- x reduce ---
    {
        float4 s4 = make_float4(0.f, 0.f, 0.f, 0.f);
        #pragma unroll 4
        for (int p = 0; p < 32; p++) {
            float4 v = __ldcg(reinterpret_cast<const float4*>(
                &g_xp[((size_t)(b*32 + p))*1024 + tid*4]));
            s4.x += v.x; s4.y += v.y; s4.z += v.z; s4.w += v.w;
        }
        *reinterpret_cast<float4*>(&xsm[tid*4]) = s4;
    }
    __syncthreads();
    // --- dpfp -> kvs; ct==0 writes Kt column ---
    #pragma unroll
    for (int it = 0; it < 8; it++) {
        int f = it*256 + tid;
        int m = f >> 7, i = f & 127;
        int im1 = (i + 127) & 127;
        float a  = (i  < 64) ? fmaxf( xsm[m*64 + i     ], 0.f)
                             : fmaxf(-xsm[m*64 + i - 64], 0.f);
        float b2 = (im1< 64) ? fmaxf( xsm[m*64 + im1     ], 0.f)
                             : fmaxf(-xsm[m*64 + im1 - 64], 0.f);
        float kk = a*b2;
        kvs[m*128 + i] = kk;
        if (ct == 0)
            __stcg(&g_Kt[(size_t)b*NDK*NDK + (size_t)i*NDK + (R + m)], kk);
    }
    __syncthreads();
    // --- t2 = k @ Kt_old (masked) ---
    {
        int r = tid & 127, h = tid >> 7;
        float a[16];
        #pragma unroll
        for (int m = 0; m < 16; m++) a[m] = 0.f;
        if (r < R) {
            #pragma unroll 8
            for (int i = h*64; i < h*64 + 64; i++) {
                float kt = __ldcg(&Ktb[i*128 + r]);
                #pragma unroll
                for (int m = 0; m < 16; m++) a[m] += kvs[m*128 + i]*kt;
            }
        }
        #pragma unroll
        for (int m = 0; m < 16; m++) Ach[(h*16 + m)*128 + r] = a[m];
    }
    __syncthreads();
    if (tid < 128) {
        int r = tid;
        #pragma unroll
        for (int m = 0; m < 16; m++)
            t2s[m*128 + r] = Ach[m*128 + r] + Ach[(16 + m)*128 + r];
    }
    __syncthreads();
    if (tid < 128) {
        int m = tid >> 3, p = tid & 7;
        float s = 0.f;
        #pragma unroll
        for (int r = p*16; r < p*16 + 16; r++) s += t2s[m*128 + r];
        red[tid] = s;
    }
    __syncthreads();
    if (tid < NM) {
        float s = 0.f;
        #pragma unroll
        for (int j2 = 0; j2 < 8; j2++) s += red[tid*8 + j2];
        kzf[tid] = s + EPSV;
    }
    __syncthreads();

    // --- prev: bulk NI load then sync-free fma2 ---
    for (int f = tid; f < R*8; f += 256) {
        int r = f >> 3, q = (f & 7)*4;
        *reinterpret_cast<float4*>(&NIa[f*4]) =
            __ldcg(reinterpret_cast<const float4*>(&NIb[(size_t)r*ND + cb + q]));
    }
    __syncthreads();
    int m = tid >> 4, cp = tid & 15, c2 = cp*2;
    u64 accp = 0ull;
    {
        const u64* NIu = reinterpret_cast<const u64*>(NIa);
        #pragma unroll 8
        for (int r = 0; r < R; r++) {
            float t = t2s[m*128 + r];
            fma2(accp, pk2(t, t), NIu[r*16 + cp]);
        }
    }
    float2 pv = up2(accp);
    float invkz = 1.f/kzf[m];
    pv.x *= invkz; pv.y *= invkz;
    __syncthreads();

    // --- k-split v/gate GEMM ---
    int kq = tid >> 5, cl = tid & 31;
    u64 accv[8], accb[8];
    #pragma unroll
    for (int mp = 0; mp < 8; mp++) { accv[mp] = 0ull; accb[mp] = 0ull; }
    const float* gmB = &g_mem[(size_t)b*ND*NM];
    const float* WvB = &Wmv[cb + cl];
    const float* WbB = &Wmb[cb + cl];
    for (int ch = 0; ch < 4; ch++) {
        int k0g = ch*256;
        #pragma unroll
        for (int it = 0; it < 4; it++) {
            int f = it*256 + tid;
            *reinterpret_cast<float4*>(&Ach[f*4]) =
                __ldcg(reinterpret_cast<const float4*>(&gmB[(size_t)k0g*NM + f*4]));
        }
        __syncthreads();
        const u64* AchU = reinterpret_cast<const u64*>(Ach);
        #pragma unroll 8
        for (int kk = 0; kk < 32; kk++) {
            int k = kq*32 + kk;
            float wv = WvB[(size_t)(k0g + k)*ND];
            float wb = WbB[(size_t)(k0g + k)*ND];
            u64 wv2 = pk2(wv, wv), wb2 = pk2(wb, wb);
            #pragma unroll
            for (int mp = 0; mp < 8; mp++) {
                u64 am = AchU[k*8 + mp];
                fma2(accv[mp], am, wv2);
                fma2(accb[mp], am, wb2);
            }
        }
        __syncthreads();
    }
    // --- two-round kq reduction (V) ---
    u64* ppu = reinterpret_cast<u64*>(pp);
    if (kq >= 4) {
        #pragma unroll
        for (int mp = 0; mp < 8; mp++) ppu[((kq-4)*8 + mp)*32 + cl] = accv[mp];
    }
    __syncthreads();
    if (kq < 4) {
        #pragma unroll
        for (int mp = 0; mp < 8; mp++) {
            float2 x = up2(accv[mp]), y = up2(ppu[(kq*8 + mp)*32 + cl]);
            ppu[(kq*8 + mp)*32 + cl] = pk2(x.x + y.x, x.y + y.y);
        }
    }
    __syncthreads();
    float vV0 = 0.f, vV1 = 0.f;
    {
        int mh = m >> 1, hf = m & 1;
        #pragma unroll
        for (int q = 0; q < 4; q++) {
            vV0 += pp[((q*8 + mh)*32 + c2    )*2 + hf];
            vV1 += pp[((q*8 + mh)*32 + c2 + 1)*2 + hf];
        }
    }
    __syncthreads();
    // --- two-round kq reduction (B) ---
    if (kq >= 4) {
        #pragma unroll
        for (int mp = 0; mp < 8; mp++) ppu[((kq-4)*8 + mp)*32 + cl] = accb[mp];
    }
    __syncthreads();
    if (kq < 4) {
        #pragma unroll
        for (int mp = 0; mp < 8; mp++) {
            float2 x = up2(accb[mp]), y = up2(ppu[(kq*8 + mp)*32 + cl]);
            ppu[(kq*8 + mp)*32 + cl] = pk2(x.x + y.x, x.y + y.y);
        }
    }
    __syncthreads();
    float vB0 = 0.f, vB1 = 0.f;
    {
        int mh = m >> 1, hf = m & 1;
        #pragma unroll
        for (int q = 0; q < 4; q++) {
            vB0 += pp[((q*8 + mh)*32 + c2    )*2 + hf];
            vB1 += pp[((q*8 + mh)*32 + c2 + 1)*2 + hf];
        }
    }
    float2 bias = *reinterpret_cast<const float2*>(&bmb[cb + c2]);
    float g0 = 1.f/(1.f + expf(-(vB0 + bias.x)));
    float g1 = 1.f/(1.f + expf(-(vB1 + bias.y)));
    float2 o = make_float2(g0*(vV0 - pv.x), g1*(vV1 - pv.y));
    __stcg(reinterpret_cast<float2*>(
        &g_NI[((size_t)b*NDK + R + m)*ND + cb + c2]), o);
    __syncthreads();

    // --- distributed tail: every block owns 4 tt ranks (balanced) ---
    if (seg < NSEG-1) {
        float* qs  = S + 2048;   // t2s dead
        float* ph2 = S + 4112;   // Ach dead: ph2[h*64 + m2*4 + rl], h<64
        size_t rb2 = (size_t)b*NS + (seg+1)*NL + (NL - NM);
        #pragma unroll
        for (int it = 0; it < 2; it++) {
            int f = it*256 + tid;
            int m2 = f >> 5; int qo = (f & 31) * 4;
            *reinterpret_cast<float4*>(&qs[m2*128 + qo]) =
                *reinterpret_cast<const float4*>(&g_Q[(rb2 + m2)*NDK + qo]);
        }
        __syncthreads();
        {
            int rl = tid & 3, h = tid >> 2;      // h: 0..63, covers i in [2h,2h+2)
            int r = ct*4 + rl;
            float a[16];
            #pragma unroll
            for (int m2 = 0; m2 < 16; m2++) a[m2] = 0.f;
            if (r < R) {
                #pragma unroll
                for (int i = h*2; i < h*2 + 2; i++) {
                    float kt = __ldcg(&Ktb[i*128 + r]);
                    #pragma unroll
                    for (int m2 = 0; m2 < 16; m2++) a[m2] += qs[m2*128 + i]*kt;
                }
            } else if (r < R + NM) {
                const float* kcol = &kvs[(r - R)*128];
                #pragma unroll
                for (int i = h*2; i < h*2 + 2; i++) {
                    float kt = kcol[i];
                    #pragma unroll
                    for (int m2 = 0; m2 < 16; m2++) a[m2] += qs[m2*128 + i]*kt;
                }
            }
            #pragma unroll
            for (int m2 = 0; m2 < 16; m2++) ph2[h*64 + m2*4 + rl] = a[m2];
        }
        __syncthreads();
        if (tid < 64) {                          // tid = m2*4 + rl
            int m2 = tid >> 2, rl = tid & 3;
            float s = 0.f;
            #pragma unroll 8
            for (int h = 0; h < 64; h++) s += ph2[h*64 + tid];
            __stcg(&g_tt[(b*NM + m2)*NDK + ct*4 + rl], s);
        }
    }
}

// ---------------- kT: T = mask(Q @ K^T)/den (zero fast path) ----------------
__global__ void kT()
{
    __shared__ float As[32*64];
    __shared__ float Bs[32*128];
    int tid = threadIdx.x;
    int r0 = blockIdx.x * 64;
    int b  = blockIdx.y;
    int maskR_max = ((r0 + 63)/NL)*NM;
    if (maskR_max == 0) {
        #pragma unroll
        for (int it = 0; it < 8; it++) {
            int f = it*256 + tid;
            int row = f >> 5; int c = (f & 31)*4;
            *reinterpret_cast<float4*>(&g_T[((size_t)b*NS + r0 + row)*NDK + c]) =
                make_float4(0.f, 0.f, 0.f, 0.f);
        }
        return;
    }
    int tx = tid & 15, ty = tid >> 4;
    u64 acc[4][4];
    #pragma unroll
    for (int i = 0; i < 4; i++)
        #pragma unroll
        for (int j = 0; j < 4; j++) acc[i][j] = 0ull;

    for (int k0 = 0; k0 < NDK; k0 += 32) {
        #pragma unroll
        for (int it = 0; it < 2; it++) {
            int f = it*256 + tid;
            int r = f >> 3; int q = (f & 7) * 4;
            float4 v4 = *reinterpret_cast<const float4*>(
                &g_Q[((size_t)b*NS + r0 + r)*NDK + k0 + q]);
            As[(q+0)*64+r] = v4.x; As[(q+1)*64+r] = v4.y;
            As[(q+2)*64+r] = v4.z; As[(q+3)*64+r] = v4.w;
        }
        #pragma unroll
        for (int it = 0; it < 4; it++) {
            int f = it*256 + tid;
            int kr = f >> 5; int c = (f & 31) * 4;
            *reinterpret_cast<float4*>(&Bs[kr*128 + c]) =
                *reinterpret_cast<const float4*>(&g_Kt[(size_t)b*NDK*NDK + (size_t)(k0+kr)*NDK + c]);
        }
        __syncthreads();
        #pragma unroll
        for (int k = 0; k < 32; k++) {
            u64 a2[4], bv[4];
            #pragma unroll
            for (int i = 0; i < 4; i++) {
                float a = As[k*64 + ty*4 + i];
                a2[i] = pk2(a, a);
            }
            #pragma unroll
            for (int j = 0; j < 4; j++)
                bv[j] = *reinterpret_cast<const u64*>(&Bs[k*128 + tx*8 + 2*j]);
            #pragma unroll
            for (int i = 0; i < 4; i++)
                #pragma unroll
                for (int j = 0; j < 4; j++) fma2(acc[i][j], a2[i], bv[j]);
        }
        __syncthreads();
    }
    #pragma unroll
    for (int i = 0; i < 4; i++) {
        int row = r0 + ty*4 + i;
        int maskR = (row / NL) * NM;
        float2 tv[4];
        float rsum = 0.f;
        #pragma unroll
        for (int j = 0; j < 4; j++) {
            float2 f = up2(acc[i][j]);
            int c0 = tx*8 + 2*j;
            if (c0     >= maskR) f.x = 0.f;
            if (c0 + 1 >= maskR) f.y = 0.f;
            rsum += f.x + f.y;
            tv[j] = f;
        }
        #pragma unroll
        for (int off = 1; off < 16; off <<= 1)
            rsum += __shfl_xor_sync(0xffffffffu, rsum, off);
        float inv = 1.f/(rsum + EPSV);
        #pragma unroll
        for (int j = 0; j < 4; j++) {
            float2 o = make_float2(tv[j].x*inv, tv[j].y*inv);
            *reinterpret_cast<float2*>(&g_T[((size_t)b*NS + row)*NDK + tx*8 + 2*j]) = o;
        }
    }
}

// ---------------- k4: out = mo + tanh(T @ NI); rank-bounded K ----------------
__global__ void __launch_bounds__(256) k4_out(const float* __restrict__ mo,
                                              float* __restrict__ out)
{
    __shared__ float As[32*128];
    __shared__ float Bs[32*128];
    int tid = threadIdx.x;
    int c0 = blockIdx.x * 128;
    int r0 = blockIdx.y * 128;
    int b  = blockIdx.z;
    int kmax = ((r0 + 127)/NL)*NM;
    if (kmax == 0) {
        #pragma unroll
        for (int it = 0; it < 16; it++) {
            int f = it*256 + tid;
            int row = f >> 5; int c = (f & 31)*4;
            size_t ix = ((size_t)b*NS + r0 + row)*ND + c0 + c;
            *reinterpret_cast<float4*>(&out[ix]) =
                *reinterpret_cast<const float4*>(&mo[ix]);
        }
        return;
    }
    int kup = (kmax + 31) & ~31;
    int w = tid >> 5, lane = tid & 31;
    u64 acc[8][4];
    #pragma unroll
    for (int rp = 0; rp < 8; rp++)
        #pragma unroll
        for (int j = 0; j < 4; j++) acc[rp][j] = 0ull;

    for (int k0 = 0; k0 < kup; k0 += 32) {
        #pragma unroll
        for (int it = 0; it < 4; it++) {
            int f = it*256 + tid;
            int row = f >> 3; int q = (f & 7) * 4;
            float4 v4 = *reinterpret_cast<const float4*>(
                &g_T[((size_t)b*NS + r0 + row)*NDK + k0 + q]);
            As[(q+0)*128+row] = v4.x; As[(q+1)*128+row] = v4.y;
            As[(q+2)*128+row] = v4.z; As[(q+3)*128+row] = v4.w;
        }
        #pragma unroll
        for (int it = 0; it < 4; it++) {
            int f = it*256 + tid;
            int kr = f >> 5; int c = (f & 31) * 4;
            *reinterpret_cast<float4*>(&Bs[kr*128 + c]) =
                *reinterpret_cast<const float4*>(
                    &g_NI[(size_t)b*NDK*ND + (size_t)(k0+kr)*ND + c0 + c]);
        }
        __syncthreads();
        #pragma unroll
        for (int k = 0; k < 32; k++) {
            u64 a2[8];
            #pragma unroll
            for (int rp = 0; rp < 8; rp++)
                a2[rp] = *reinterpret_cast<const u64*>(&As[k*128 + w*16 + 2*rp]);
            #pragma unroll
            for (int j = 0; j < 4; j++) {
                float bv = Bs[k*128 + lane + 32*j];
                u64 b2 = pk2(bv, bv);
                #pragma unroll
                for (int rp = 0; rp < 8; rp++) fma2(acc[rp][j], a2[rp], b2);
            }
        }
        __syncthreads();
    }
    #pragma unroll
    for (int rp = 0; rp < 8; rp++) {
        int r = r0 + w*16 + 2*rp;
        #pragma unroll
        for (int j = 0; j < 4; j++) {
            int c = c0 + lane + 32*j;
            float2 f = up2(acc[rp][j]);
            size_t i0 = ((size_t)b*NS + r)*ND + c;
            size_t i1 = i0 + ND;
            out[i0] = mo[i0] + tanh_hw(f.x);
            out[i1] = mo[i1] + tanh_hw(f.y);
        }
    }
}

// ---------------- launch ----------------
extern "C" void kernel_launch(void* const* d_in, const int* in_sizes, int n_in,
                              void* d_out, int out_size)
{
    const float* hs  = (const float*)d_in[0];
    const float* mo  = (const float*)d_in[1];
    const float* Wmq = (const float*)d_in[2];
    const float* Wmk = (const float*)d_in[3];
    const float* Wmv = (const float*)d_in[4];
    const float* Wmb = (const float*)d_in[5];
    const float* bmb = (const float*)d_in[6];
    float* out = (float*)d_out;

    k0_projq<<<132, 256>>>(hs, Wmq);
    for (int seg = 0; seg < NSEG; seg++) {
        kA<<<128, 256>>>(mo, Wmk, seg);
        kC<<<128, 256>>>(Wmv, Wmb, bmb, seg);
    }
    kT<<<dim3(66, 4), 256>>>();
    k4_out<<<dim3(8, 33, 4), 256>>>(mo, out);
}